// round 1
// baseline (speedup 1.0000x reference)
#include <cuda_runtime.h>
#include <math.h>

#define B_   8
#define S_   512
#define DIN  1024
#define DOUT 1024
#define H_   8
#define DATT 128

// Scratch (device globals: no allocation allowed)
__device__ float g_xp[B_ * S_ * DOUT];        // projected x  (16 MB)
__device__ float g_e2[B_ * H_ * S_];          // exp(s2 - max) per (b,h,j)
__device__ float g_denom[B_ * H_ * S_];       // per-row softmax denominator
__device__ float g_colsum[B_ * DOUT];         // column sums of xp (uniform fallback)

// ---------------------------------------------------------------------------
// Kernel 1: xp = x @ W    (M=4096, N=1024, K=1024), classic 128x128x8 SGEMM
// ---------------------------------------------------------------------------
__global__ __launch_bounds__(256) void sgemm_xw(const float* __restrict__ A,
                                                const float* __restrict__ Bm) {
    const int M = B_ * S_, N = DOUT, K = DIN;
    const int BM = 128, BN = 128, BK = 8, TM = 8, TN = 8;
    __shared__ float As[BK][BM];
    __shared__ float Bs[BK][BN];

    int tid  = threadIdx.x;
    int brow = blockIdx.y, bcol = blockIdx.x;
    const float* Ab = A + (size_t)brow * BM * K;
    const float* Bb = Bm + bcol * BN;

    int arow  = tid >> 1, acol = (tid & 1) * 4;   // A: 128 rows x 8 cols
    int browi = tid >> 5, bcoli = (tid & 31) * 4; // B: 8 rows x 128 cols
    int trow  = (tid >> 4) * TM, tcol = (tid & 15) * TN;

    float acc[TM][TN] = {};
    for (int k0 = 0; k0 < K; k0 += BK) {
        float4 av = *(const float4*)(Ab + (size_t)arow * K + k0 + acol);
        As[acol + 0][arow] = av.x;
        As[acol + 1][arow] = av.y;
        As[acol + 2][arow] = av.z;
        As[acol + 3][arow] = av.w;
        float4 bv = *(const float4*)(Bb + (size_t)(k0 + browi) * N + bcoli);
        *(float4*)&Bs[browi][bcoli] = bv;
        __syncthreads();
#pragma unroll
        for (int k = 0; k < BK; k++) {
            float ra[TM], rb[TN];
#pragma unroll
            for (int i = 0; i < TM; i++) ra[i] = As[k][trow + i];
#pragma unroll
            for (int j = 0; j < TN; j++) rb[j] = Bs[k][tcol + j];
#pragma unroll
            for (int i = 0; i < TM; i++)
#pragma unroll
                for (int j = 0; j < TN; j++)
                    acc[i][j] = fmaf(ra[i], rb[j], acc[i][j]);
        }
        __syncthreads();
    }
#pragma unroll
    for (int i = 0; i < TM; i++)
#pragma unroll
        for (int j = 0; j < TN; j += 4) {
            float4 v = make_float4(acc[i][j], acc[i][j + 1], acc[i][j + 2], acc[i][j + 3]);
            *(float4*)(g_xp + (size_t)(brow * BM + trow + i) * N + bcol * BN + tcol + j) = v;
        }
}

// ---------------------------------------------------------------------------
// Kernel 2a: s2[b,h,j] = dot(xp[b,j,h*128: h*128+128], att_w[128:256])
//            one warp per (b,h,j); stored temporarily into g_e2
// ---------------------------------------------------------------------------
__global__ __launch_bounds__(256) void s2_kernel(const float* __restrict__ attw) {
    int gw   = (blockIdx.x * 256 + threadIdx.x) >> 5;  // global warp id
    int lane = threadIdx.x & 31;
    int j  = gw % S_;
    int bh = gw / S_;
    int h  = bh % H_;
    int b  = bh / H_;
    const float* row = g_xp + ((size_t)(b * S_ + j)) * DOUT + h * DATT;
    const float* w2  = attw + DATT;
    int d = lane * 4;  // 32 lanes * 4 = 128 = DATT, single step
    float4 xv = *(const float4*)(row + d);
    float4 wv = *(const float4*)(w2 + d);
    float s = xv.x * wv.x + xv.y * wv.y + xv.z * wv.z + xv.w * wv.w;
#pragma unroll
    for (int o = 16; o; o >>= 1) s += __shfl_xor_sync(0xFFFFFFFFu, s, o);
    if (lane == 0) g_e2[(size_t)(b * H_ + h) * S_ + j] = s;
}

// ---------------------------------------------------------------------------
// Kernel 2b: per (b,h): m = max_j s2 ; e2 = exp(s2 - m)     (512 threads)
// ---------------------------------------------------------------------------
__global__ __launch_bounds__(512) void exp_kernel() {
    int bh = blockIdx.x;
    __shared__ float red[16];
    float v = g_e2[(size_t)bh * S_ + threadIdx.x];
    float m = v;
#pragma unroll
    for (int o = 16; o; o >>= 1) m = fmaxf(m, __shfl_xor_sync(0xFFFFFFFFu, m, o));
    int wid = threadIdx.x >> 5, lane = threadIdx.x & 31;
    if (lane == 0) red[wid] = m;
    __syncthreads();
    if (wid == 0) {
        float t = (lane < 16) ? red[lane] : -INFINITY;
#pragma unroll
        for (int o = 8; o; o >>= 1) t = fmaxf(t, __shfl_xor_sync(0xFFFFFFFFu, t, o));
        if (lane == 0) red[0] = t;
    }
    __syncthreads();
    m = red[0];
    g_e2[(size_t)bh * S_ + threadIdx.x] = expf(v - m);
}

// ---------------------------------------------------------------------------
// Kernel 3: denom[b,h,i] = mask_i * sum_j (adj[b,i,j]>0 && mask_j>0) * e2[b,h,j]
//           one block per (b,i); warp w handles head w
// ---------------------------------------------------------------------------
__global__ __launch_bounds__(256) void denom_kernel(const int* __restrict__ adj,
                                                    const float* __restrict__ mask) {
    int bi = blockIdx.x;
    int b = bi >> 9, i = bi & 511;
    int wid = threadIdx.x >> 5, lane = threadIdx.x & 31;  // wid = head
    const int*   arow = adj + ((size_t)(b * S_ + i)) * S_;
    const float* e2h  = g_e2 + (size_t)(b * H_ + wid) * S_;
    const float* mk   = mask + b * S_;
    float mi = mk[i] > 0.f ? 1.f : 0.f;
    float s = 0.f;
    for (int j = lane; j < S_; j += 32)
        if (arow[j] > 0 && mk[j] > 0.f) s += e2h[j];
#pragma unroll
    for (int o = 16; o; o >>= 1) s += __shfl_xor_sync(0xFFFFFFFFu, s, o);
    if (lane == 0) g_denom[(size_t)(b * H_ + wid) * S_ + i] = s * mi;
}

// ---------------------------------------------------------------------------
// Kernel 4: colsum[b,c] = sum_j xp[b,j,c]   (uniform-softmax fallback)
// ---------------------------------------------------------------------------
__global__ __launch_bounds__(256) void colsum_kernel() {
    int idx = blockIdx.x * 256 + threadIdx.x;  // B_ * DOUT
    int b = idx >> 10, c = idx & 1023;
    const float* p = g_xp + (size_t)b * S_ * DOUT + c;
    float s = 0.f;
    for (int j = 0; j < S_; j++) s += p[(size_t)j * DOUT];
    g_colsum[idx] = s;
}

// ---------------------------------------------------------------------------
// Kernel 5: out[b,i,c] (unnormalized) = sum_j valid(b,i,j) * e2[b,h(c),j] * xp[b,j,c]
//           per-batch 512x1024x512 SGEMM; BN=128 => each block column is one head
// ---------------------------------------------------------------------------
__global__ __launch_bounds__(256) void sgemm_att(const int* __restrict__ adj,
                                                 const float* __restrict__ mask,
                                                 float* __restrict__ out) {
    const int N = DOUT, K = S_;
    const int BM = 128, BN = 128, BK = 8, TM = 8, TN = 8;
    __shared__ float As[BK][BM];
    __shared__ float Bs[BK][BN];

    int b = blockIdx.z;
    int tid = threadIdx.x;
    int brow = blockIdx.y, bcol = blockIdx.x;  // bcol == head (BN == DATT)

    const int*   adjb  = adj + (size_t)b * S_ * S_ + (size_t)brow * BM * S_;
    const float* xpb   = g_xp + (size_t)b * S_ * DOUT + bcol * BN;
    const float* mk    = mask + b * S_;
    const float* e2h   = g_e2 + (size_t)(b * H_ + bcol) * S_;
    float*       outb  = out + (size_t)b * S_ * DOUT;

    int arow  = tid >> 1, acol = (tid & 1) * 4;
    int browi = tid >> 5, bcoli = (tid & 31) * 4;
    int trow  = (tid >> 4) * TM, tcol = (tid & 15) * TN;

    float mi = mk[brow * BM + arow] > 0.f ? 1.f : 0.f;

    float acc[TM][TN] = {};
    for (int k0 = 0; k0 < K; k0 += BK) {
        int4 av = *(const int4*)(adjb + (size_t)arow * S_ + k0 + acol);
        As[acol + 0][arow] = (av.x > 0) ? mi : 0.f;
        As[acol + 1][arow] = (av.y > 0) ? mi : 0.f;
        As[acol + 2][arow] = (av.z > 0) ? mi : 0.f;
        As[acol + 3][arow] = (av.w > 0) ? mi : 0.f;
        int j = k0 + browi;
        float scale = (mk[j] > 0.f) ? e2h[j] : 0.f;
        float4 bv = *(const float4*)(xpb + (size_t)j * N + bcoli);
        bv.x *= scale; bv.y *= scale; bv.z *= scale; bv.w *= scale;
        *(float4*)&Bs[browi][bcoli] = bv;
        __syncthreads();
#pragma unroll
        for (int k = 0; k < BK; k++) {
            float ra[TM], rb[TN];
#pragma unroll
            for (int i = 0; i < TM; i++) ra[i] = As[k][trow + i];
#pragma unroll
            for (int j2 = 0; j2 < TN; j2++) rb[j2] = Bs[k][tcol + j2];
#pragma unroll
            for (int i = 0; i < TM; i++)
#pragma unroll
                for (int j2 = 0; j2 < TN; j2++)
                    acc[i][j2] = fmaf(ra[i], rb[j2], acc[i][j2]);
        }
        __syncthreads();
    }
#pragma unroll
    for (int i = 0; i < TM; i++)
#pragma unroll
        for (int j2 = 0; j2 < TN; j2 += 4) {
            float4 v = make_float4(acc[i][j2], acc[i][j2 + 1], acc[i][j2 + 2], acc[i][j2 + 3]);
            *(float4*)(outb + (size_t)(brow * BM + trow + i) * N + bcol * BN + tcol + j2) = v;
        }
}

// ---------------------------------------------------------------------------
// Kernel 6: normalize: out /= denom ; fully-masked rows -> uniform mean
// ---------------------------------------------------------------------------
__global__ __launch_bounds__(256) void norm_kernel(float* __restrict__ out) {
    int idx = blockIdx.x * 256 + threadIdx.x;  // B_*S_*DOUT
    int c  = idx & 1023;
    int bi = idx >> 10;
    int i  = bi & 511;
    int b  = bi >> 9;
    float d = g_denom[(size_t)(b * H_ + (c >> 7)) * S_ + i];
    float v = out[idx];
    out[idx] = (d > 0.f) ? (v / d) : g_colsum[(b << 10) | c] * (1.0f / S_);
}

// ---------------------------------------------------------------------------
extern "C" void kernel_launch(void* const* d_in, const int* in_sizes, int n_in,
                              void* d_out, int out_size) {
    const float* x    = (const float*)d_in[0];  // [B,S,DIN]
    const float* mask = (const float*)d_in[1];  // [B,S]
    const int*   adj  = (const int*)d_in[2];    // [B,S,S]
    const float* W    = (const float*)d_in[3];  // [DIN,DOUT]
    const float* attw = (const float*)d_in[4];  // [2*DATT]
    // d_in[5] = att_b: cancels in softmax, unused
    float* out = (float*)d_out;

    sgemm_xw<<<dim3(DOUT / 128, (B_ * S_) / 128), 256>>>(x, W);
    s2_kernel<<<(B_ * H_ * S_) / 8, 256>>>(attw);
    exp_kernel<<<B_ * H_, 512>>>();
    denom_kernel<<<B_ * S_, 256>>>(adj, mask);
    colsum_kernel<<<(B_ * DOUT) / 256, 256>>>();
    sgemm_att<<<dim3(DOUT / 128, S_ / 128, B_), 256>>>(adj, mask, out);
    norm_kernel<<<(B_ * S_ * DOUT) / 256, 256>>>(out);
}

// round 2
// speedup vs baseline: 1.1352x; 1.1352x over previous
#include <cuda_runtime.h>
#include <math.h>

#define B_   8
#define S_   512
#define DIN  1024
#define DOUT 1024
#define H_   8
#define DATT 128

// Scratch (device globals: no allocation allowed)
__device__ float g_xp[B_ * S_ * DOUT];        // projected x  (16 MB)
__device__ float g_e2[B_ * H_ * S_];          // masked exp(s2 - max) per (b,h,j)
__device__ float g_denom[B_ * H_ * S_];       // per-row softmax denominator
__device__ float g_colsum[B_ * DOUT];         // column sums of xp (uniform fallback)

// ---------------------------------------------------------------------------
// Packed fp32x2 FMA helpers (Blackwell f32x2 pipe; exact fp32 semantics)
// ---------------------------------------------------------------------------
__device__ __forceinline__ unsigned long long ffma2(unsigned long long a,
                                                    unsigned long long b,
                                                    unsigned long long c) {
    unsigned long long d;
    asm("fma.rn.f32x2 %0, %1, %2, %3;" : "=l"(d) : "l"(a), "l"(b), "l"(c));
    return d;
}
__device__ __forceinline__ unsigned long long pack2(float x) {
    unsigned long long r;
    asm("mov.b64 %0, {%1, %1};" : "=l"(r) : "f"(x));
    return r;
}

// ---------------------------------------------------------------------------
// Kernel 1: xp = x @ W    (M=4096, N=1024, K=1024), 128x128x8 with FFMA2
// ---------------------------------------------------------------------------
__global__ __launch_bounds__(256) void sgemm_xw(const float* __restrict__ A,
                                                const float* __restrict__ Bm) {
    const int N = DOUT, K = DIN;
    const int BM = 128, BN = 128, BK = 8, TM = 8, TN = 8;
    __shared__ __align__(16) float As[BK][BM];
    __shared__ __align__(16) float Bs[BK][BN];

    int tid  = threadIdx.x;
    int brow = blockIdx.y, bcol = blockIdx.x;
    const float* Ab = A + (size_t)brow * BM * K;
    const float* Bb = Bm + bcol * BN;

    int arow  = tid >> 1, acol = (tid & 1) * 4;   // A: 128 rows x 8 cols
    int browi = tid >> 5, bcoli = (tid & 31) * 4; // B: 8 rows x 128 cols
    int trow  = (tid >> 4) * TM, tcol = (tid & 15) * TN;

    unsigned long long acc2[TM][TN / 2] = {};
    for (int k0 = 0; k0 < K; k0 += BK) {
        float4 av = *(const float4*)(Ab + (size_t)arow * K + k0 + acol);
        As[acol + 0][arow] = av.x;
        As[acol + 1][arow] = av.y;
        As[acol + 2][arow] = av.z;
        As[acol + 3][arow] = av.w;
        float4 bv = *(const float4*)(Bb + (size_t)(k0 + browi) * N + bcoli);
        *(float4*)&Bs[browi][bcoli] = bv;
        __syncthreads();
#pragma unroll
        for (int k = 0; k < BK; k++) {
            unsigned long long ra2[TM], rb2[TN / 2];
#pragma unroll
            for (int i = 0; i < TM; i++) ra2[i] = pack2(As[k][trow + i]);
#pragma unroll
            for (int j = 0; j < TN / 2; j++)
                rb2[j] = *(const unsigned long long*)(&Bs[k][tcol + 2 * j]);
#pragma unroll
            for (int i = 0; i < TM; i++)
#pragma unroll
                for (int j = 0; j < TN / 2; j++)
                    acc2[i][j] = ffma2(ra2[i], rb2[j], acc2[i][j]);
        }
        __syncthreads();
    }
#pragma unroll
    for (int i = 0; i < TM; i++) {
        float2 p0 = *(float2*)&acc2[i][0];
        float2 p1 = *(float2*)&acc2[i][1];
        float2 p2 = *(float2*)&acc2[i][2];
        float2 p3 = *(float2*)&acc2[i][3];
        float* dst = g_xp + (size_t)(brow * BM + trow + i) * N + bcol * BN + tcol;
        *(float4*)(dst + 0) = make_float4(p0.x, p0.y, p1.x, p1.y);
        *(float4*)(dst + 4) = make_float4(p2.x, p2.y, p3.x, p3.y);
    }
}

// ---------------------------------------------------------------------------
// Kernel 2a: s2[b,h,j] = dot(xp[b,j,h*128:...], att_w[128:256]); one warp each
// ---------------------------------------------------------------------------
__global__ __launch_bounds__(256) void s2_kernel(const float* __restrict__ attw) {
    int gw   = (blockIdx.x * 256 + threadIdx.x) >> 5;
    int lane = threadIdx.x & 31;
    int j  = gw % S_;
    int bh = gw / S_;
    int h  = bh % H_;
    int b  = bh / H_;
    const float* row = g_xp + ((size_t)(b * S_ + j)) * DOUT + h * DATT;
    const float* w2  = attw + DATT;
    int d = lane * 4;
    float4 xv = *(const float4*)(row + d);
    float4 wv = *(const float4*)(w2 + d);
    float s = xv.x * wv.x + xv.y * wv.y + xv.z * wv.z + xv.w * wv.w;
#pragma unroll
    for (int o = 16; o; o >>= 1) s += __shfl_xor_sync(0xFFFFFFFFu, s, o);
    if (lane == 0) g_e2[(size_t)(b * H_ + h) * S_ + j] = s;
}

// ---------------------------------------------------------------------------
// Kernel 2b: per (b,h): m = max_j s2 ; e2 = mask_j * exp(s2 - m)
// ---------------------------------------------------------------------------
__global__ __launch_bounds__(512) void exp_kernel(const float* __restrict__ mask) {
    int bh = blockIdx.x;
    int b  = bh >> 3;
    __shared__ float red[16];
    float v = g_e2[(size_t)bh * S_ + threadIdx.x];
    float m = v;
#pragma unroll
    for (int o = 16; o; o >>= 1) m = fmaxf(m, __shfl_xor_sync(0xFFFFFFFFu, m, o));
    int wid = threadIdx.x >> 5, lane = threadIdx.x & 31;
    if (lane == 0) red[wid] = m;
    __syncthreads();
    if (wid == 0) {
        float t = (lane < 16) ? red[lane] : -INFINITY;
#pragma unroll
        for (int o = 8; o; o >>= 1) t = fmaxf(t, __shfl_xor_sync(0xFFFFFFFFu, t, o));
        if (lane == 0) red[0] = t;
    }
    __syncthreads();
    m = red[0];
    float mj = mask[b * S_ + threadIdx.x] > 0.f ? 1.f : 0.f;
    g_e2[(size_t)bh * S_ + threadIdx.x] = mj * expf(v - m);
}

// ---------------------------------------------------------------------------
// Kernel 3: denom[b,h,i] = mi * sum_j (adj[b,i,j]>0) * e2m[b,h,j]
//   Block = (b, 32-row tile). All 8 heads' masked e2 staged in smem (16 KB).
//   Coalesced scalar adjacency loads; lane-consecutive conflict-free LDS.
// ---------------------------------------------------------------------------
__global__ __launch_bounds__(256) void denom_kernel(const int* __restrict__ adj,
                                                    const float* __restrict__ mask) {
    __shared__ float e2s[H_][S_];
    int blk = blockIdx.x;
    int b   = blk >> 4;          // 16 row-tiles per batch
    int i0  = (blk & 15) * 32;
    int tid = threadIdx.x;
    // stage all heads' e2 (masked) for this batch: 4096 floats
    {
        const float4* src = (const float4*)(g_e2 + (size_t)b * H_ * S_);
        float4* dst = (float4*)&e2s[0][0];
        for (int t = tid; t < H_ * S_ / 4; t += 256) dst[t] = src[t];
    }
    __syncthreads();

    int wid = tid >> 5, lane = tid & 31;
    const float* mk = mask + b * S_;
#pragma unroll 1
    for (int r = 0; r < 4; r++) {
        int i = i0 + wid * 4 + r;
        const int* arow = adj + ((size_t)(b * S_ + i)) * S_;
        float s[H_] = {};
#pragma unroll
        for (int it = 0; it < 16; it++) {
            int j = it * 32 + lane;
            if (arow[j] > 0) {
#pragma unroll
                for (int h = 0; h < H_; h++) s[h] += e2s[h][j];
            }
        }
        float mi = mk[i] > 0.f ? 1.f : 0.f;
#pragma unroll
        for (int h = 0; h < H_; h++) {
            float v = s[h];
#pragma unroll
            for (int o = 16; o; o >>= 1) v += __shfl_xor_sync(0xFFFFFFFFu, v, o);
            if (lane == 0) g_denom[(size_t)(b * H_ + h) * S_ + i] = v * mi;
        }
    }
}

// ---------------------------------------------------------------------------
// Kernel 4: colsum[b,c] = sum_j xp[b,j,c]   (uniform-softmax fallback)
// ---------------------------------------------------------------------------
__global__ __launch_bounds__(256) void colsum_kernel() {
    int idx = blockIdx.x * 256 + threadIdx.x;  // B_ * DOUT
    int b = idx >> 10, c = idx & 1023;
    const float* p = g_xp + (size_t)b * S_ * DOUT + c;
    float s = 0.f;
    for (int j = 0; j < S_; j++) s += p[(size_t)j * DOUT];
    g_colsum[idx] = s;
}

// ---------------------------------------------------------------------------
// Kernel 5: out[b,i,c] (unnorm) = sum_j valid(b,i,j) * e2m[b,h(c),j] * xp[b,j,c]
//           per-batch 512x1024x512; BN=128 => block column == head; FFMA2
// ---------------------------------------------------------------------------
__global__ __launch_bounds__(256) void sgemm_att(const int* __restrict__ adj,
                                                 const float* __restrict__ mask,
                                                 float* __restrict__ out) {
    const int N = DOUT, K = S_;
    const int BM = 128, BN = 128, BK = 8, TM = 8, TN = 8;
    __shared__ __align__(16) float As[BK][BM];
    __shared__ __align__(16) float Bs[BK][BN];

    int b = blockIdx.z;
    int tid = threadIdx.x;
    int brow = blockIdx.y, bcol = blockIdx.x;  // bcol == head

    const int*   adjb  = adj + (size_t)b * S_ * S_ + (size_t)brow * BM * S_;
    const float* xpb   = g_xp + (size_t)b * S_ * DOUT + bcol * BN;
    const float* mk    = mask + b * S_;
    const float* e2h   = g_e2 + (size_t)(b * H_ + bcol) * S_;
    float*       outb  = out + (size_t)b * S_ * DOUT;

    int arow  = tid >> 1, acol = (tid & 1) * 4;
    int browi = tid >> 5, bcoli = (tid & 31) * 4;
    int trow  = (tid >> 4) * TM, tcol = (tid & 15) * TN;

    float mi = mk[brow * BM + arow] > 0.f ? 1.f : 0.f;

    unsigned long long acc2[TM][TN / 2] = {};
    for (int k0 = 0; k0 < K; k0 += BK) {
        int4 av = *(const int4*)(adjb + (size_t)arow * S_ + k0 + acol);
        As[acol + 0][arow] = (av.x > 0) ? mi : 0.f;
        As[acol + 1][arow] = (av.y > 0) ? mi : 0.f;
        As[acol + 2][arow] = (av.z > 0) ? mi : 0.f;
        As[acol + 3][arow] = (av.w > 0) ? mi : 0.f;
        int j = k0 + browi;
        float scale = e2h[j];  // mask already folded into e2
        float4 bv = *(const float4*)(xpb + (size_t)j * N + bcoli);
        bv.x *= scale; bv.y *= scale; bv.z *= scale; bv.w *= scale;
        *(float4*)&Bs[browi][bcoli] = bv;
        __syncthreads();
#pragma unroll
        for (int k = 0; k < BK; k++) {
            unsigned long long ra2[TM], rb2[TN / 2];
#pragma unroll
            for (int i = 0; i < TM; i++) ra2[i] = pack2(As[k][trow + i]);
#pragma unroll
            for (int j2 = 0; j2 < TN / 2; j2++)
                rb2[j2] = *(const unsigned long long*)(&Bs[k][tcol + 2 * j2]);
#pragma unroll
            for (int i = 0; i < TM; i++)
#pragma unroll
                for (int j2 = 0; j2 < TN / 2; j2++)
                    acc2[i][j2] = ffma2(ra2[i], rb2[j2], acc2[i][j2]);
        }
        __syncthreads();
    }
#pragma unroll
    for (int i = 0; i < TM; i++) {
        float2 p0 = *(float2*)&acc2[i][0];
        float2 p1 = *(float2*)&acc2[i][1];
        float2 p2 = *(float2*)&acc2[i][2];
        float2 p3 = *(float2*)&acc2[i][3];
        float* dst = outb + (size_t)(brow * BM + trow + i) * N + bcol * BN + tcol;
        *(float4*)(dst + 0) = make_float4(p0.x, p0.y, p1.x, p1.y);
        *(float4*)(dst + 4) = make_float4(p2.x, p2.y, p3.x, p3.y);
    }
}

// ---------------------------------------------------------------------------
// Kernel 6: normalize: out /= denom ; fully-masked rows -> uniform mean
// ---------------------------------------------------------------------------
__global__ __launch_bounds__(256) void norm_kernel(float* __restrict__ out) {
    int idx = blockIdx.x * 256 + threadIdx.x;  // B_*S_*DOUT
    int c  = idx & 1023;
    int bi = idx >> 10;
    int i  = bi & 511;
    int b  = bi >> 9;
    float d = g_denom[(size_t)(b * H_ + (c >> 7)) * S_ + i];
    float v = out[idx];
    out[idx] = (d > 0.f) ? (v / d) : g_colsum[(b << 10) | c] * (1.0f / S_);
}

// ---------------------------------------------------------------------------
extern "C" void kernel_launch(void* const* d_in, const int* in_sizes, int n_in,
                              void* d_out, int out_size) {
    const float* x    = (const float*)d_in[0];  // [B,S,DIN]
    const float* mask = (const float*)d_in[1];  // [B,S]
    const int*   adj  = (const int*)d_in[2];    // [B,S,S]
    const float* W    = (const float*)d_in[3];  // [DIN,DOUT]
    const float* attw = (const float*)d_in[4];  // [2*DATT]
    // d_in[5] = att_b: cancels in softmax, unused
    float* out = (float*)d_out;

    sgemm_xw<<<dim3(DOUT / 128, (B_ * S_) / 128), 256>>>(x, W);
    s2_kernel<<<(B_ * H_ * S_) / 8, 256>>>(attw);
    exp_kernel<<<B_ * H_, 512>>>(mask);
    denom_kernel<<<B_ * (S_ / 32), 256>>>(adj, mask);
    colsum_kernel<<<(B_ * DOUT) / 256, 256>>>();
    sgemm_att<<<dim3(DOUT / 128, S_ / 128, B_), 256>>>(adj, mask, out);
    norm_kernel<<<(B_ * S_ * DOUT) / 256, 256>>>(out);
}

// round 4
// speedup vs baseline: 2.3661x; 2.0842x over previous
#include <cuda_runtime.h>
#include <cuda_bf16.h>
#include <math.h>
#include <stdint.h>

#define B_   8
#define S_   512
#define DIN  1024
#define DOUT 1024
#define H_   8
#define DATT 128
#define NTOK (B_ * S_)   // 4096

// ---------------- device scratch (no allocation allowed) ----------------
__device__ __align__(16) float    g_xp[NTOK * DOUT];        // projected x [token][chan] 16MB
__device__ __align__(16) float    g_e2[B_ * H_ * S_];       // masked exp(s2 - max)
__device__ __align__(16) float    g_denom[B_ * H_ * S_];    // softmax denominators
__device__ __align__(16) float    g_colsum[B_ * DOUT];      // column sums (fallback)
__device__ __align__(16) uint16_t g_xh[NTOK * DIN];         // x hi bf16
__device__ __align__(16) uint16_t g_xl[NTOK * DIN];         // x lo bf16
__device__ __align__(16) uint16_t g_wth[DOUT * DIN];        // W^T hi bf16 [n][k]
__device__ __align__(16) uint16_t g_wtl[DOUT * DIN];        // W^T lo bf16
__device__ __align__(16) uint16_t g_xsth[DOUT * NTOK];      // (e2*xp)^T hi bf16 [c][token]
__device__ __align__(16) uint16_t g_xstl[DOUT * NTOK];      // (e2*xp)^T lo bf16
__device__ __align__(16) uint16_t g_adjbf[B_ * S_ * S_];    // valid adjacency bf16 [b][i][j]

// ---------------------------- helpers ----------------------------
__device__ __forceinline__ uint32_t smem_u32(const void* p) {
    uint32_t a;
    asm("{ .reg .u64 t; cvta.to.shared.u64 t, %1; cvt.u32.u64 %0, t; }" : "=r"(a) : "l"(p));
    return a;
}
__device__ __forceinline__ uint32_t swz(uint32_t off) { return off ^ ((off >> 3) & 0x70); }

__device__ __forceinline__ void sts128(uint32_t addr, uint4 v) {
    asm volatile("st.shared.v4.b32 [%0], {%1,%2,%3,%4};"
                 :: "r"(addr), "r"(v.x), "r"(v.y), "r"(v.z), "r"(v.w));
}
__device__ __forceinline__ void ldsm4(uint32_t& r0, uint32_t& r1, uint32_t& r2, uint32_t& r3,
                                      uint32_t addr) {
    asm volatile("ldmatrix.sync.aligned.m8n8.x4.shared.b16 {%0,%1,%2,%3}, [%4];"
                 : "=r"(r0), "=r"(r1), "=r"(r2), "=r"(r3) : "r"(addr));
}
__device__ __forceinline__ void mma_bf16(float* c, const uint32_t* a, uint32_t b0, uint32_t b1) {
    asm volatile(
        "mma.sync.aligned.m16n8k16.row.col.f32.bf16.bf16.f32 "
        "{%0,%1,%2,%3}, {%4,%5,%6,%7}, {%8,%9}, {%0,%1,%2,%3};"
        : "+f"(c[0]), "+f"(c[1]), "+f"(c[2]), "+f"(c[3])
        : "r"(a[0]), "r"(a[1]), "r"(a[2]), "r"(a[3]), "r"(b0), "r"(b1));
}
__device__ __forceinline__ uint16_t bf16_bits(float f) {
    __nv_bfloat16 h = __float2bfloat16_rn(f);
    return *(uint16_t*)&h;
}
__device__ __forceinline__ float bf16_val(uint16_t b) {
    __nv_bfloat16 h = *(__nv_bfloat16*)&b;
    return __bfloat162float(h);
}
__device__ __forceinline__ void split_bf16(float x, uint16_t& hb, uint16_t& lb) {
    hb = bf16_bits(x);
    lb = bf16_bits(x - bf16_val(hb));
}
__device__ __forceinline__ void split2(float x0, float x1, uint32_t& hi, uint32_t& lo) {
    uint16_t h0, l0, h1, l1;
    split_bf16(x0, h0, l0);
    split_bf16(x1, h1, l1);
    hi = (uint32_t)h0 | ((uint32_t)h1 << 16);
    lo = (uint32_t)l0 | ((uint32_t)l1 << 16);
}

// ============================================================================
// Pre-pass 1: x -> hi/lo bf16 (elementwise, 8 elems/thread)
// ============================================================================
__global__ __launch_bounds__(256) void xsplit_in(const float* __restrict__ src) {
    size_t base = ((size_t)blockIdx.x * 256 + threadIdx.x) * 8;
    float4 v0 = *(const float4*)(src + base);
    float4 v1 = *(const float4*)(src + base + 4);
    uint32_t h0, l0, h1, l1, h2, l2, h3, l3;
    split2(v0.x, v0.y, h0, l0);
    split2(v0.z, v0.w, h1, l1);
    split2(v1.x, v1.y, h2, l2);
    split2(v1.z, v1.w, h3, l3);
    *(uint4*)(g_xh + base) = make_uint4(h0, h1, h2, h3);
    *(uint4*)(g_xl + base) = make_uint4(l0, l1, l2, l3);
}

// ============================================================================
// Pre-pass 2: W [k][n] -> W^T hi/lo bf16 [n][k] (tiled transpose + split)
// ============================================================================
__global__ __launch_bounds__(256) void wsplit(const float* __restrict__ W) {
    __shared__ float tile[32][33];
    int tx = threadIdx.x, ty = threadIdx.y;
    int n0 = blockIdx.x * 32, k0 = blockIdx.y * 32;
#pragma unroll
    for (int i = 0; i < 4; i++)
        tile[ty + i * 8][tx] = W[(size_t)(k0 + ty + i * 8) * DOUT + n0 + tx];
    __syncthreads();
#pragma unroll
    for (int i = 0; i < 4; i++) {
        int n = n0 + ty + i * 8, k = k0 + tx;
        float v = tile[tx][ty + i * 8];
        uint16_t h, l;
        split_bf16(v, h, l);
        g_wth[(size_t)n * DIN + k] = h;
        g_wtl[(size_t)n * DIN + k] = l;
    }
}

// ============================================================================
// Kernel 3: projection GEMM  g_xp[m][n] = sum_k x[m][k] W[k][n]
//   BM=128, BN=128, BK=64, 8 warps (4x2), warp tile 32x64, bf16x3 split HMMA
// ============================================================================
#define PROJ_SMEM (4 * 16384 + 128)
__global__ __launch_bounds__(256) void proj_mma() {
    extern __shared__ char dsm[];
    uint32_t sb = (smem_u32(dsm) + 127) & ~127u;
    const uint32_t AH = sb, AL = sb + 16384, BH = sb + 32768, BL = sb + 49152;

    int tid = threadIdx.x, lane = tid & 31, wid = tid >> 5;
    int wm = wid & 3, wn = wid >> 2;
    int m_base = blockIdx.y * 128, n_base = blockIdx.x * 128;

    float acc[2][8][4] = {};

    for (int kc = 0; kc < 16; kc++) {
        // stage A (x hi/lo): 128 rows x 64 k
#pragma unroll
        for (int it = 0; it < 4; it++) {
            int idx = it * 256 + tid;
            int row = idx >> 3, kg = idx & 7;
            size_t goff = (size_t)(m_base + row) * DIN + kc * 64 + kg * 8;
            uint4 vh = *(const uint4*)(g_xh + goff);
            uint4 vl = *(const uint4*)(g_xl + goff);
            uint32_t soff = swz((uint32_t)(row * 128 + kg * 16));
            sts128(AH + soff, vh);
            sts128(AL + soff, vl);
        }
        // stage B (W^T hi/lo): 128 n-rows x 64 k
#pragma unroll
        for (int it = 0; it < 4; it++) {
            int idx = it * 256 + tid;
            int row = idx >> 3, kg = idx & 7;
            size_t goff = (size_t)(n_base + row) * DIN + kc * 64 + kg * 8;
            uint4 vh = *(const uint4*)(g_wth + goff);
            uint4 vl = *(const uint4*)(g_wtl + goff);
            uint32_t soff = swz((uint32_t)(row * 128 + kg * 16));
            sts128(BH + soff, vh);
            sts128(BL + soff, vl);
        }
        __syncthreads();
#pragma unroll
        for (int ks = 0; ks < 4; ks++) {
            uint32_t ah[2][4], al[2][4];
#pragma unroll
            for (int mt = 0; mt < 2; mt++) {
                int r = wm * 32 + mt * 16 + (lane & 15);
                int kb = ks * 32 + (lane >> 4) * 16;
                uint32_t off = swz((uint32_t)(r * 128 + kb));
                ldsm4(ah[mt][0], ah[mt][1], ah[mt][2], ah[mt][3], AH + off);
                ldsm4(al[mt][0], al[mt][1], al[mt][2], al[mt][3], AL + off);
            }
#pragma unroll
            for (int nq = 0; nq < 4; nq++) {
                int r = wn * 64 + nq * 16 + (lane & 7) + ((lane >> 4) & 1) * 8;
                int kb = ks * 32 + ((lane >> 3) & 1) * 16;
                uint32_t off = swz((uint32_t)(r * 128 + kb));
                uint32_t bh[4], bl[4];
                ldsm4(bh[0], bh[1], bh[2], bh[3], BH + off);
                ldsm4(bl[0], bl[1], bl[2], bl[3], BL + off);
#pragma unroll
                for (int mt = 0; mt < 2; mt++) {
                    mma_bf16(acc[mt][nq * 2],     ah[mt], bh[0], bh[1]);
                    mma_bf16(acc[mt][nq * 2],     ah[mt], bl[0], bl[1]);
                    mma_bf16(acc[mt][nq * 2],     al[mt], bh[0], bh[1]);
                    mma_bf16(acc[mt][nq * 2 + 1], ah[mt], bh[2], bh[3]);
                    mma_bf16(acc[mt][nq * 2 + 1], ah[mt], bl[2], bl[3]);
                    mma_bf16(acc[mt][nq * 2 + 1], al[mt], bh[2], bh[3]);
                }
            }
        }
        __syncthreads();
    }
#pragma unroll
    for (int mt = 0; mt < 2; mt++)
#pragma unroll
        for (int nt = 0; nt < 8; nt++) {
            int r = m_base + wm * 32 + mt * 16 + (lane >> 2);
            int c = n_base + wn * 64 + nt * 8 + (lane & 3) * 2;
            float* a4 = acc[mt][nt];
            *(float2*)(g_xp + (size_t)r * DOUT + c) = make_float2(a4[0], a4[1]);
            *(float2*)(g_xp + (size_t)(r + 8) * DOUT + c) = make_float2(a4[2], a4[3]);
        }
}

// ============================================================================
// Kernel 4: s2[b,h,j] = dot(xp[b,j,h*128:...], att_w[128:256]); one warp each
// ============================================================================
__global__ __launch_bounds__(256) void s2_kernel(const float* __restrict__ attw) {
    int gw = (blockIdx.x * 256 + threadIdx.x) >> 5;
    int lane = threadIdx.x & 31;
    int j = gw % S_;
    int bh = gw / S_;
    int h = bh % H_, b = bh / H_;
    const float* row = g_xp + ((size_t)(b * S_ + j)) * DOUT + h * DATT;
    const float* w2 = attw + DATT;
    int d = lane * 4;
    float4 xv = *(const float4*)(row + d);
    float4 wv = *(const float4*)(w2 + d);
    float s = xv.x * wv.x + xv.y * wv.y + xv.z * wv.z + xv.w * wv.w;
#pragma unroll
    for (int o = 16; o; o >>= 1) s += __shfl_xor_sync(0xFFFFFFFFu, s, o);
    if (lane == 0) g_e2[(size_t)(b * H_ + h) * S_ + j] = s;
}

// ============================================================================
// Kernel 5: per (b,h): m = max_j s2 ; e2 = mask_j * exp(s2 - m)
// ============================================================================
__global__ __launch_bounds__(512) void exp_kernel(const float* __restrict__ mask) {
    int bh = blockIdx.x;
    int b = bh >> 3;
    __shared__ float red[16];
    float v = g_e2[(size_t)bh * S_ + threadIdx.x];
    float m = v;
#pragma unroll
    for (int o = 16; o; o >>= 1) m = fmaxf(m, __shfl_xor_sync(0xFFFFFFFFu, m, o));
    int wid = threadIdx.x >> 5, lane = threadIdx.x & 31;
    if (lane == 0) red[wid] = m;
    __syncthreads();
    if (wid == 0) {
        float t = (lane < 16) ? red[lane] : -INFINITY;
#pragma unroll
        for (int o = 8; o; o >>= 1) t = fmaxf(t, __shfl_xor_sync(0xFFFFFFFFu, t, o));
        if (lane == 0) red[0] = t;
    }
    __syncthreads();
    m = red[0];
    float mj = mask[b * S_ + threadIdx.x] > 0.f ? 1.f : 0.f;
    g_e2[(size_t)bh * S_ + threadIdx.x] = mj * expf(v - m);
}

// ============================================================================
// Kernel 6: colsum[b,c] = sum_j xp[b,j,c]
// ============================================================================
__global__ __launch_bounds__(256) void colsum_kernel() {
    int idx = blockIdx.x * 256 + threadIdx.x;  // B_*DOUT
    int b = idx >> 10, c = idx & 1023;
    const float* p = g_xp + (size_t)b * S_ * DOUT + c;
    float s = 0.f;
    for (int j = 0; j < S_; j++) s += p[(size_t)j * DOUT];
    g_colsum[idx] = s;
}

// ============================================================================
// Kernel 7: denom[b,h,i] = mi * sum_j (adj>0)*e2[b,h,j]
// ============================================================================
__global__ __launch_bounds__(256) void denom_kernel(const int* __restrict__ adj,
                                                    const float* __restrict__ mask) {
    __shared__ float e2s[H_][S_];
    int blk = blockIdx.x;
    int b = blk >> 4;
    int i0 = (blk & 15) * 32;
    int tid = threadIdx.x;
    {
        const float4* src = (const float4*)(g_e2 + (size_t)b * H_ * S_);
        float4* dst = (float4*)&e2s[0][0];
        for (int t = tid; t < H_ * S_ / 4; t += 256) dst[t] = src[t];
    }
    __syncthreads();
    int wid = tid >> 5, lane = tid & 31;
    const float* mk = mask + b * S_;
#pragma unroll 1
    for (int r = 0; r < 4; r++) {
        int i = i0 + wid * 4 + r;
        const int* arow = adj + ((size_t)(b * S_ + i)) * S_;
        float s[H_] = {};
#pragma unroll
        for (int it = 0; it < 16; it++) {
            int j = it * 32 + lane;
            if (arow[j] > 0) {
#pragma unroll
                for (int h = 0; h < H_; h++) s[h] += e2s[h][j];
            }
        }
        float mi = mk[i] > 0.f ? 1.f : 0.f;
#pragma unroll
        for (int h = 0; h < H_; h++) {
            float v = s[h];
#pragma unroll
            for (int o = 16; o; o >>= 1) v += __shfl_xor_sync(0xFFFFFFFFu, v, o);
            if (lane == 0) g_denom[(size_t)(b * H_ + h) * S_ + i] = v * mi;
        }
    }
}

// ============================================================================
// Pre-pass 8: adjbf[b][i][j] = (adj>0 && mask_i>0) ? 1.0bf16 : 0
// ============================================================================
__global__ __launch_bounds__(256) void adjbf_kernel(const int* __restrict__ adj,
                                                    const float* __restrict__ mask) {
    size_t base = ((size_t)blockIdx.x * 256 + threadIdx.x) * 8;
    int bi = (int)(base >> 9);  // b*512 + i
    uint32_t one = (mask[bi] > 0.f) ? 0x3F80u : 0u;
    int4 a0 = *(const int4*)(adj + base);
    int4 a1 = *(const int4*)(adj + base + 4);
    uint32_t p0 = ((a0.x > 0) ? one : 0u) | (((a0.y > 0) ? one : 0u) << 16);
    uint32_t p1 = ((a0.z > 0) ? one : 0u) | (((a0.w > 0) ? one : 0u) << 16);
    uint32_t p2 = ((a1.x > 0) ? one : 0u) | (((a1.y > 0) ? one : 0u) << 16);
    uint32_t p3 = ((a1.z > 0) ? one : 0u) | (((a1.w > 0) ? one : 0u) << 16);
    *(uint4*)(g_adjbf + base) = make_uint4(p0, p1, p2, p3);
}

// ============================================================================
// Pre-pass 9: xsT[c][token] = split(e2[b,h(c),j] * xp[token][c]) (transpose)
// ============================================================================
__global__ __launch_bounds__(256) void xsplit_s() {
    __shared__ float tile[32][33];
    int tx = threadIdx.x, ty = threadIdx.y;
    int j0 = blockIdx.x * 32, c0 = blockIdx.y * 32;
#pragma unroll
    for (int i = 0; i < 4; i++)
        tile[ty + i * 8][tx] = g_xp[(size_t)(j0 + ty + i * 8) * DOUT + c0 + tx];
    __syncthreads();
#pragma unroll
    for (int i = 0; i < 4; i++) {
        int c = c0 + ty + i * 8;
        int j = j0 + tx;                   // global token index
        int b = j >> 9, h = c >> 7;
        float e = g_e2[(size_t)(b * H_ + h) * S_ + (j & 511)];
        float v = tile[tx][ty + i * 8] * e;
        uint16_t hb, lb;
        split_bf16(v, hb, lb);
        g_xsth[(size_t)c * NTOK + j] = hb;
        g_xstl[(size_t)c * NTOK + j] = lb;
    }
}

// ============================================================================
// Kernel 10: attention GEMM + fused normalize
//   out[b,i,c] = (sum_j adjbf[i][j] * xs[c][j]) / denom   (or colsum/S fallback)
//   BM=128(i), BN=128(c)=one head, BK=64(j); A exact bf16, B hi/lo -> 2 MMAs
// ============================================================================
#define ATT_SMEM (3 * 16384 + 128)
__global__ __launch_bounds__(256) void att_mma(float* __restrict__ out) {
    extern __shared__ char dsm[];
    uint32_t sb = (smem_u32(dsm) + 127) & ~127u;
    const uint32_t AD = sb, BH = sb + 16384, BL = sb + 32768;

    int tid = threadIdx.x, lane = tid & 31, wid = tid >> 5;
    int wm = wid & 3, wn = wid >> 2;
    int h = blockIdx.x, i0 = blockIdx.y * 128, b = blockIdx.z;
    int c0 = h * DATT;

    float acc[2][8][4] = {};

    for (int kc = 0; kc < 8; kc++) {
        // stage A (adjacency bf16): rows i, 64 j
#pragma unroll
        for (int it = 0; it < 4; it++) {
            int idx = it * 256 + tid;
            int row = idx >> 3, kg = idx & 7;
            size_t goff = (size_t)(b * S_ + i0 + row) * S_ + kc * 64 + kg * 8;
            uint4 v = *(const uint4*)(g_adjbf + goff);
            sts128(AD + swz((uint32_t)(row * 128 + kg * 16)), v);
        }
        // stage B (scaled values hi/lo): rows c, 64 j
#pragma unroll
        for (int it = 0; it < 4; it++) {
            int idx = it * 256 + tid;
            int row = idx >> 3, kg = idx & 7;
            size_t goff = (size_t)(c0 + row) * NTOK + b * S_ + kc * 64 + kg * 8;
            uint4 vh = *(const uint4*)(g_xsth + goff);
            uint4 vl = *(const uint4*)(g_xstl + goff);
            uint32_t soff = swz((uint32_t)(row * 128 + kg * 16));
            sts128(BH + soff, vh);
            sts128(BL + soff, vl);
        }
        __syncthreads();
#pragma unroll
        for (int ks = 0; ks < 4; ks++) {
            uint32_t ad[2][4];
#pragma unroll
            for (int mt = 0; mt < 2; mt++) {
                int r = wm * 32 + mt * 16 + (lane & 15);
                int kb = ks * 32 + (lane >> 4) * 16;
                ldsm4(ad[mt][0], ad[mt][1], ad[mt][2], ad[mt][3],
                      AD + swz((uint32_t)(r * 128 + kb)));
            }
#pragma unroll
            for (int nq = 0; nq < 4; nq++) {
                int r = wn * 64 + nq * 16 + (lane & 7) + ((lane >> 4) & 1) * 8;
                int kb = ks * 32 + ((lane >> 3) & 1) * 16;
                uint32_t off = swz((uint32_t)(r * 128 + kb));
                uint32_t bh[4], bl[4];
                ldsm4(bh[0], bh[1], bh[2], bh[3], BH + off);
                ldsm4(bl[0], bl[1], bl[2], bl[3], BL + off);
#pragma unroll
                for (int mt = 0; mt < 2; mt++) {
                    mma_bf16(acc[mt][nq * 2],     ad[mt], bh[0], bh[1]);
                    mma_bf16(acc[mt][nq * 2],     ad[mt], bl[0], bl[1]);
                    mma_bf16(acc[mt][nq * 2 + 1], ad[mt], bh[2], bh[3]);
                    mma_bf16(acc[mt][nq * 2 + 1], ad[mt], bl[2], bl[3]);
                }
            }
        }
        __syncthreads();
    }

    // epilogue: normalize + fallback, coalesced-ish float2 stores
    const float* dh = g_denom + (size_t)(b * H_ + h) * S_;
    const float* cs = g_colsum + (b << 10);
#pragma unroll
    for (int mt = 0; mt < 2; mt++) {
        int r0 = i0 + wm * 32 + mt * 16 + (lane >> 2);
        float d0 = dh[r0], d1 = dh[r0 + 8];
        float q0 = (d0 > 0.f) ? (1.0f / d0) : 0.f;
        float q1 = (d1 > 0.f) ? (1.0f / d1) : 0.f;
#pragma unroll
        for (int nt = 0; nt < 8; nt++) {
            int c = c0 + wn * 64 + nt * 8 + (lane & 3) * 2;
            float* a4 = acc[mt][nt];
            float2 o0, o1;
            if (d0 > 0.f) { o0 = make_float2(a4[0] * q0, a4[1] * q0); }
            else {
                float2 f = *(const float2*)(cs + c);
                o0 = make_float2(f.x * (1.0f / S_), f.y * (1.0f / S_));
            }
            if (d1 > 0.f) { o1 = make_float2(a4[2] * q1, a4[3] * q1); }
            else {
                float2 f = *(const float2*)(cs + c);
                o1 = make_float2(f.x * (1.0f / S_), f.y * (1.0f / S_));
            }
            *(float2*)(out + (size_t)(b * S_ + r0) * DOUT + c) = o0;
            *(float2*)(out + (size_t)(b * S_ + r0 + 8) * DOUT + c) = o1;
        }
    }
}

// ============================================================================
extern "C" void kernel_launch(void* const* d_in, const int* in_sizes, int n_in,
                              void* d_out, int out_size) {
    const float* x    = (const float*)d_in[0];  // [B,S,DIN]
    const float* mask = (const float*)d_in[1];  // [B,S]
    const int*   adj  = (const int*)d_in[2];    // [B,S,S]
    const float* W    = (const float*)d_in[3];  // [DIN,DOUT]
    const float* attw = (const float*)d_in[4];  // [2*DATT]
    float* out = (float*)d_out;

    cudaFuncSetAttribute(proj_mma, cudaFuncAttributeMaxDynamicSharedMemorySize, PROJ_SMEM);
    cudaFuncSetAttribute(att_mma, cudaFuncAttributeMaxDynamicSharedMemorySize, ATT_SMEM);

    xsplit_in<<<(NTOK * DIN) / (256 * 8), 256>>>(x);
    wsplit<<<dim3(DOUT / 32, DIN / 32), dim3(32, 8)>>>(W);
    adjbf_kernel<<<(B_ * S_ * S_) / (256 * 8), 256>>>(adj, mask);
    proj_mma<<<dim3(DOUT / 128, NTOK / 128), 256, PROJ_SMEM>>>();
    s2_kernel<<<(B_ * H_ * S_) / 8, 256>>>(attw);
    exp_kernel<<<B_ * H_, 512>>>(mask);
    colsum_kernel<<<(B_ * DOUT) / 256, 256>>>();
    denom_kernel<<<B_ * (S_ / 32), 256>>>(adj, mask);
    xsplit_s<<<dim3(NTOK / 32, DOUT / 32), dim3(32, 8)>>>();
    att_mma<<<dim3(H_, S_ / 128, B_), 256, ATT_SMEM>>>(out);
}

// round 5
// speedup vs baseline: 2.9567x; 1.2496x over previous
#include <cuda_runtime.h>
#include <cuda_bf16.h>
#include <math.h>
#include <stdint.h>

#define B_   8
#define S_   512
#define DIN  1024
#define DOUT 1024
#define H_   8
#define DATT 128
#define NTOK (B_ * S_)   // 4096

// ---------------- device scratch (no allocation allowed) ----------------
__device__ __align__(16) float    g_xp[NTOK * DOUT];        // projected x [token][chan] 16MB
__device__ __align__(16) float    g_e2[B_ * H_ * S_];       // masked exp(s2 - max)
__device__ __align__(16) float    g_denom[B_ * H_ * S_];    // softmax denominators
__device__ __align__(16) float    g_colsum[B_ * DOUT];      // column sums (fallback)
__device__ __align__(16) uint16_t g_xh[NTOK * DIN];         // x hi bf16
__device__ __align__(16) uint16_t g_xl[NTOK * DIN];         // x lo bf16
__device__ __align__(16) uint16_t g_wth[DOUT * DIN];        // W^T hi bf16 [n][k]
__device__ __align__(16) uint16_t g_wtl[DOUT * DIN];        // W^T lo bf16
__device__ __align__(16) uint16_t g_xsth[DOUT * NTOK];      // (e2*xp)^T hi bf16 [c][token]
__device__ __align__(16) uint16_t g_xstl[DOUT * NTOK];      // (e2*xp)^T lo bf16
__device__ __align__(16) uint16_t g_adjbf[B_ * S_ * S_];    // valid adjacency bf16 [b][i][j]

// ---------------------------- helpers ----------------------------
__device__ __forceinline__ uint32_t smem_u32(const void* p) {
    uint32_t a;
    asm("{ .reg .u64 t; cvta.to.shared.u64 t, %1; cvt.u32.u64 %0, t; }" : "=r"(a) : "l"(p));
    return a;
}
__device__ __forceinline__ uint32_t swz(uint32_t off) { return off ^ ((off >> 3) & 0x70); }

__device__ __forceinline__ void cpasync16(uint32_t smem, const void* gmem) {
    asm volatile("cp.async.cg.shared.global [%0], [%1], 16;" :: "r"(smem), "l"(gmem));
}
__device__ __forceinline__ void cp_commit() {
    asm volatile("cp.async.commit_group;" ::: "memory");
}
template <int N>
__device__ __forceinline__ void cp_wait() {
    asm volatile("cp.async.wait_group %0;" :: "n"(N) : "memory");
}
__device__ __forceinline__ void ldsm4(uint32_t& r0, uint32_t& r1, uint32_t& r2, uint32_t& r3,
                                      uint32_t addr) {
    asm volatile("ldmatrix.sync.aligned.m8n8.x4.shared.b16 {%0,%1,%2,%3}, [%4];"
                 : "=r"(r0), "=r"(r1), "=r"(r2), "=r"(r3) : "r"(addr));
}
__device__ __forceinline__ void mma_bf16(float* c, const uint32_t* a, uint32_t b0, uint32_t b1) {
    asm volatile(
        "mma.sync.aligned.m16n8k16.row.col.f32.bf16.bf16.f32 "
        "{%0,%1,%2,%3}, {%4,%5,%6,%7}, {%8,%9}, {%0,%1,%2,%3};"
        : "+f"(c[0]), "+f"(c[1]), "+f"(c[2]), "+f"(c[3])
        : "r"(a[0]), "r"(a[1]), "r"(a[2]), "r"(a[3]), "r"(b0), "r"(b1));
}
__device__ __forceinline__ uint16_t bf16_bits(float f) {
    __nv_bfloat16 h = __float2bfloat16_rn(f);
    return *(uint16_t*)&h;
}
__device__ __forceinline__ float bf16_val(uint16_t b) {
    __nv_bfloat16 h = *(__nv_bfloat16*)&b;
    return __bfloat162float(h);
}
__device__ __forceinline__ void split_bf16(float x, uint16_t& hb, uint16_t& lb) {
    hb = bf16_bits(x);
    lb = bf16_bits(x - bf16_val(hb));
}
__device__ __forceinline__ void split2(float x0, float x1, uint32_t& hi, uint32_t& lo) {
    uint16_t h0, l0, h1, l1;
    split_bf16(x0, h0, l0);
    split_bf16(x1, h1, l1);
    hi = (uint32_t)h0 | ((uint32_t)h1 << 16);
    lo = (uint32_t)l0 | ((uint32_t)l1 << 16);
}

// ============================================================================
// Pre-pass 1: x -> hi/lo bf16 (elementwise, 8 elems/thread)
// ============================================================================
__global__ __launch_bounds__(256) void xsplit_in(const float* __restrict__ src) {
    size_t base = ((size_t)blockIdx.x * 256 + threadIdx.x) * 8;
    float4 v0 = *(const float4*)(src + base);
    float4 v1 = *(const float4*)(src + base + 4);
    uint32_t h0, l0, h1, l1, h2, l2, h3, l3;
    split2(v0.x, v0.y, h0, l0);
    split2(v0.z, v0.w, h1, l1);
    split2(v1.x, v1.y, h2, l2);
    split2(v1.z, v1.w, h3, l3);
    *(uint4*)(g_xh + base) = make_uint4(h0, h1, h2, h3);
    *(uint4*)(g_xl + base) = make_uint4(l0, l1, l2, l3);
}

// ============================================================================
// Pre-pass 2: W [k][n] -> W^T hi/lo bf16 [n][k] (tiled transpose + split)
// ============================================================================
__global__ __launch_bounds__(256) void wsplit(const float* __restrict__ W) {
    __shared__ float tile[32][33];
    int tx = threadIdx.x, ty = threadIdx.y;
    int n0 = blockIdx.x * 32, k0 = blockIdx.y * 32;
#pragma unroll
    for (int i = 0; i < 4; i++)
        tile[ty + i * 8][tx] = W[(size_t)(k0 + ty + i * 8) * DOUT + n0 + tx];
    __syncthreads();
#pragma unroll
    for (int i = 0; i < 4; i++) {
        int n = n0 + ty + i * 8, k = k0 + tx;
        float v = tile[tx][ty + i * 8];
        uint16_t h, l;
        split_bf16(v, h, l);
        g_wth[(size_t)n * DIN + k] = h;
        g_wtl[(size_t)n * DIN + k] = l;
    }
}

// ============================================================================
// Kernel 3: projection GEMM  g_xp[m][n] = sum_k x[m][k] W[k][n]
//   BM=128, BN=128, BK=64, 2-stage cp.async pipeline, bf16x3 split HMMA
// ============================================================================
#define PROJ_STAGE 65536
#define PROJ_SMEM (2 * PROJ_STAGE + 128)
__global__ __launch_bounds__(256) void proj_mma() {
    extern __shared__ char dsm[];
    uint32_t sb = (smem_u32(dsm) + 127) & ~127u;

    int tid = threadIdx.x, lane = tid & 31, wid = tid >> 5;
    int wm = wid & 3, wn = wid >> 2;
    int m_base = blockIdx.y * 128, n_base = blockIdx.x * 128;

    // per-thread staging coords (fixed across chunks)
    int srow = tid >> 3, skg = tid & 7;
    uint32_t soff = swz((uint32_t)(srow * 128 + skg * 16));

    auto stage = [&](int ck, int s) {
        uint32_t base = sb + (uint32_t)s * PROJ_STAGE;
#pragma unroll
        for (int it = 0; it < 4; it++) {
            int row = srow + it * 32;
            uint32_t so = swz((uint32_t)(row * 128 + skg * 16));
            size_t ga = (size_t)(m_base + row) * DIN + ck * 64 + skg * 8;
            cpasync16(base + so, g_xh + ga);
            cpasync16(base + 16384 + so, g_xl + ga);
            size_t gb = (size_t)(n_base + row) * DIN + ck * 64 + skg * 8;
            cpasync16(base + 32768 + so, g_wth + gb);
            cpasync16(base + 49152 + so, g_wtl + gb);
        }
        cp_commit();
    };
    (void)soff;

    float acc[2][8][4] = {};

    stage(0, 0);
    for (int ck = 0; ck < 16; ck++) {
        if (ck + 1 < 16) {
            stage(ck + 1, (ck + 1) & 1);
            cp_wait<1>();
        } else {
            cp_wait<0>();
        }
        __syncthreads();
        uint32_t AH = sb + (uint32_t)(ck & 1) * PROJ_STAGE;
        uint32_t AL = AH + 16384, BH = AH + 32768, BL = AH + 49152;
#pragma unroll
        for (int ks = 0; ks < 4; ks++) {
            uint32_t ah[2][4], al[2][4];
#pragma unroll
            for (int mt = 0; mt < 2; mt++) {
                int r = wm * 32 + mt * 16 + (lane & 15);
                int kb = ks * 32 + (lane >> 4) * 16;
                uint32_t off = swz((uint32_t)(r * 128 + kb));
                ldsm4(ah[mt][0], ah[mt][1], ah[mt][2], ah[mt][3], AH + off);
                ldsm4(al[mt][0], al[mt][1], al[mt][2], al[mt][3], AL + off);
            }
#pragma unroll
            for (int nq = 0; nq < 4; nq++) {
                int r = wn * 64 + nq * 16 + (lane & 7) + ((lane >> 4) & 1) * 8;
                int kb = ks * 32 + ((lane >> 3) & 1) * 16;
                uint32_t off = swz((uint32_t)(r * 128 + kb));
                uint32_t bh[4], bl[4];
                ldsm4(bh[0], bh[1], bh[2], bh[3], BH + off);
                ldsm4(bl[0], bl[1], bl[2], bl[3], BL + off);
#pragma unroll
                for (int mt = 0; mt < 2; mt++) {
                    mma_bf16(acc[mt][nq * 2],     ah[mt], bh[0], bh[1]);
                    mma_bf16(acc[mt][nq * 2],     ah[mt], bl[0], bl[1]);
                    mma_bf16(acc[mt][nq * 2],     al[mt], bh[0], bh[1]);
                    mma_bf16(acc[mt][nq * 2 + 1], ah[mt], bh[2], bh[3]);
                    mma_bf16(acc[mt][nq * 2 + 1], ah[mt], bl[2], bl[3]);
                    mma_bf16(acc[mt][nq * 2 + 1], al[mt], bh[2], bh[3]);
                }
            }
        }
        __syncthreads();
    }
#pragma unroll
    for (int mt = 0; mt < 2; mt++)
#pragma unroll
        for (int nt = 0; nt < 8; nt++) {
            int r = m_base + wm * 32 + mt * 16 + (lane >> 2);
            int c = n_base + wn * 64 + nt * 8 + (lane & 3) * 2;
            float* a4 = acc[mt][nt];
            *(float2*)(g_xp + (size_t)r * DOUT + c) = make_float2(a4[0], a4[1]);
            *(float2*)(g_xp + (size_t)(r + 8) * DOUT + c) = make_float2(a4[2], a4[3]);
        }
}

// ============================================================================
// Kernel 4: s2[b,h,j] = dot(xp[b,j,h*128:...], att_w[128:256]); one warp each
// ============================================================================
__global__ __launch_bounds__(256) void s2_kernel(const float* __restrict__ attw) {
    int gw = (blockIdx.x * 256 + threadIdx.x) >> 5;
    int lane = threadIdx.x & 31;
    int j = gw % S_;
    int bh = gw / S_;
    int h = bh % H_, b = bh / H_;
    const float* row = g_xp + ((size_t)(b * S_ + j)) * DOUT + h * DATT;
    const float* w2 = attw + DATT;
    int d = lane * 4;
    float4 xv = *(const float4*)(row + d);
    float4 wv = *(const float4*)(w2 + d);
    float s = xv.x * wv.x + xv.y * wv.y + xv.z * wv.z + xv.w * wv.w;
#pragma unroll
    for (int o = 16; o; o >>= 1) s += __shfl_xor_sync(0xFFFFFFFFu, s, o);
    if (lane == 0) g_e2[(size_t)(b * H_ + h) * S_ + j] = s;
}

// ============================================================================
// Kernel 5: per (b,h): m = max_j s2 ; e2 = mask_j * exp(s2 - m)
// ============================================================================
__global__ __launch_bounds__(512) void exp_kernel(const float* __restrict__ mask) {
    int bh = blockIdx.x;
    int b = bh >> 3;
    __shared__ float red[16];
    float v = g_e2[(size_t)bh * S_ + threadIdx.x];
    float m = v;
#pragma unroll
    for (int o = 16; o; o >>= 1) m = fmaxf(m, __shfl_xor_sync(0xFFFFFFFFu, m, o));
    int wid = threadIdx.x >> 5, lane = threadIdx.x & 31;
    if (lane == 0) red[wid] = m;
    __syncthreads();
    if (wid == 0) {
        float t = (lane < 16) ? red[lane] : -INFINITY;
#pragma unroll
        for (int o = 8; o; o >>= 1) t = fmaxf(t, __shfl_xor_sync(0xFFFFFFFFu, t, o));
        if (lane == 0) red[0] = t;
    }
    __syncthreads();
    m = red[0];
    float mj = mask[b * S_ + threadIdx.x] > 0.f ? 1.f : 0.f;
    g_e2[(size_t)bh * S_ + threadIdx.x] = mj * expf(v - m);
}

// ============================================================================
// Kernel 6: colsum[b,c] = sum_j xp[b,j,c]
// ============================================================================
__global__ __launch_bounds__(256) void colsum_kernel() {
    int idx = blockIdx.x * 256 + threadIdx.x;  // B_*DOUT
    int b = idx >> 10, c = idx & 1023;
    const float* p = g_xp + (size_t)b * S_ * DOUT + c;
    float s = 0.f;
    for (int j = 0; j < S_; j++) s += p[(size_t)j * DOUT];
    g_colsum[idx] = s;
}

// ============================================================================
// Kernel 7: denom[b,h,i] = mi * sum_j (adj>0)*e2[b,h,j]
// ============================================================================
__global__ __launch_bounds__(256) void denom_kernel(const int* __restrict__ adj,
                                                    const float* __restrict__ mask) {
    __shared__ float e2s[H_][S_];
    int blk = blockIdx.x;
    int b = blk >> 4;
    int i0 = (blk & 15) * 32;
    int tid = threadIdx.x;
    {
        const float4* src = (const float4*)(g_e2 + (size_t)b * H_ * S_);
        float4* dst = (float4*)&e2s[0][0];
        for (int t = tid; t < H_ * S_ / 4; t += 256) dst[t] = src[t];
    }
    __syncthreads();
    int wid = tid >> 5, lane = tid & 31;
    const float* mk = mask + b * S_;
#pragma unroll 1
    for (int r = 0; r < 4; r++) {
        int i = i0 + wid * 4 + r;
        const int* arow = adj + ((size_t)(b * S_ + i)) * S_;
        float s[H_] = {};
#pragma unroll
        for (int it = 0; it < 16; it++) {
            int j = it * 32 + lane;
            if (arow[j] > 0) {
#pragma unroll
                for (int h = 0; h < H_; h++) s[h] += e2s[h][j];
            }
        }
        float mi = mk[i] > 0.f ? 1.f : 0.f;
#pragma unroll
        for (int h = 0; h < H_; h++) {
            float v = s[h];
#pragma unroll
            for (int o = 16; o; o >>= 1) v += __shfl_xor_sync(0xFFFFFFFFu, v, o);
            if (lane == 0) g_denom[(size_t)(b * H_ + h) * S_ + i] = v * mi;
        }
    }
}

// ============================================================================
// Pre-pass 8: adjbf[b][i][j] = (adj>0 && mask_i>0) ? 1.0bf16 : 0
// ============================================================================
__global__ __launch_bounds__(256) void adjbf_kernel(const int* __restrict__ adj,
                                                    const float* __restrict__ mask) {
    size_t base = ((size_t)blockIdx.x * 256 + threadIdx.x) * 8;
    int bi = (int)(base >> 9);  // b*512 + i
    uint32_t one = (mask[bi] > 0.f) ? 0x3F80u : 0u;
    int4 a0 = *(const int4*)(adj + base);
    int4 a1 = *(const int4*)(adj + base + 4);
    uint32_t p0 = ((a0.x > 0) ? one : 0u) | (((a0.y > 0) ? one : 0u) << 16);
    uint32_t p1 = ((a0.z > 0) ? one : 0u) | (((a0.w > 0) ? one : 0u) << 16);
    uint32_t p2 = ((a1.x > 0) ? one : 0u) | (((a1.y > 0) ? one : 0u) << 16);
    uint32_t p3 = ((a1.z > 0) ? one : 0u) | (((a1.w > 0) ? one : 0u) << 16);
    *(uint4*)(g_adjbf + base) = make_uint4(p0, p1, p2, p3);
}

// ============================================================================
// Pre-pass 9: xsT[c][token] = split(e2[b,h(c),j] * xp[token][c]) (transpose)
// ============================================================================
__global__ __launch_bounds__(256) void xsplit_s() {
    __shared__ float tile[32][33];
    int tx = threadIdx.x, ty = threadIdx.y;
    int j0 = blockIdx.x * 32, c0 = blockIdx.y * 32;
#pragma unroll
    for (int i = 0; i < 4; i++)
        tile[ty + i * 8][tx] = g_xp[(size_t)(j0 + ty + i * 8) * DOUT + c0 + tx];
    __syncthreads();
#pragma unroll
    for (int i = 0; i < 4; i++) {
        int c = c0 + ty + i * 8;
        int j = j0 + tx;                   // global token index
        int b = j >> 9, h = c >> 7;
        float e = g_e2[(size_t)(b * H_ + h) * S_ + (j & 511)];
        float v = tile[tx][ty + i * 8] * e;
        uint16_t hb, lb;
        split_bf16(v, hb, lb);
        g_xsth[(size_t)c * NTOK + j] = hb;
        g_xstl[(size_t)c * NTOK + j] = lb;
    }
}

// ============================================================================
// Kernel 10: attention GEMM + fused normalize, 2-stage cp.async pipeline
//   out[b,i,c] = (sum_j adjbf[i][j] * xs[c][j]) / denom   (or colsum/S fallback)
//   BM=128(i), BN=128(c)=one head, BK=64(j); A exact bf16, B hi/lo -> 2 MMAs
// ============================================================================
#define ATT_STAGE 49152
#define ATT_SMEM (2 * ATT_STAGE + 128)
__global__ __launch_bounds__(256) void att_mma(float* __restrict__ out) {
    extern __shared__ char dsm[];
    uint32_t sb = (smem_u32(dsm) + 127) & ~127u;

    int tid = threadIdx.x, lane = tid & 31, wid = tid >> 5;
    int wm = wid & 3, wn = wid >> 2;
    int h = blockIdx.x, i0 = blockIdx.y * 128, b = blockIdx.z;
    int c0 = h * DATT;

    int srow = tid >> 3, skg = tid & 7;

    auto stage = [&](int ck, int s) {
        uint32_t base = sb + (uint32_t)s * ATT_STAGE;
#pragma unroll
        for (int it = 0; it < 4; it++) {
            int row = srow + it * 32;
            uint32_t so = swz((uint32_t)(row * 128 + skg * 16));
            size_t ga = (size_t)(b * S_ + i0 + row) * S_ + ck * 64 + skg * 8;
            cpasync16(base + so, g_adjbf + ga);
            size_t gb = (size_t)(c0 + row) * NTOK + b * S_ + ck * 64 + skg * 8;
            cpasync16(base + 16384 + so, g_xsth + gb);
            cpasync16(base + 32768 + so, g_xstl + gb);
        }
        cp_commit();
    };

    float acc[2][8][4] = {};

    stage(0, 0);
    for (int kc = 0; kc < 8; kc++) {
        if (kc + 1 < 8) {
            stage(kc + 1, (kc + 1) & 1);
            cp_wait<1>();
        } else {
            cp_wait<0>();
        }
        __syncthreads();
        uint32_t AD = sb + (uint32_t)(kc & 1) * ATT_STAGE;
        uint32_t BH = AD + 16384, BL = AD + 32768;
#pragma unroll
        for (int ks = 0; ks < 4; ks++) {
            uint32_t ad[2][4];
#pragma unroll
            for (int mt = 0; mt < 2; mt++) {
                int r = wm * 32 + mt * 16 + (lane & 15);
                int kb = ks * 32 + (lane >> 4) * 16;
                ldsm4(ad[mt][0], ad[mt][1], ad[mt][2], ad[mt][3],
                      AD + swz((uint32_t)(r * 128 + kb)));
            }
#pragma unroll
            for (int nq = 0; nq < 4; nq++) {
                int r = wn * 64 + nq * 16 + (lane & 7) + ((lane >> 4) & 1) * 8;
                int kb = ks * 32 + ((lane >> 3) & 1) * 16;
                uint32_t off = swz((uint32_t)(r * 128 + kb));
                uint32_t bh[4], bl[4];
                ldsm4(bh[0], bh[1], bh[2], bh[3], BH + off);
                ldsm4(bl[0], bl[1], bl[2], bl[3], BL + off);
#pragma unroll
                for (int mt = 0; mt < 2; mt++) {
                    mma_bf16(acc[mt][nq * 2],     ad[mt], bh[0], bh[1]);
                    mma_bf16(acc[mt][nq * 2],     ad[mt], bl[0], bl[1]);
                    mma_bf16(acc[mt][nq * 2 + 1], ad[mt], bh[2], bh[3]);
                    mma_bf16(acc[mt][nq * 2 + 1], ad[mt], bl[2], bl[3]);
                }
            }
        }
        __syncthreads();
    }

    // epilogue: normalize + fallback
    const float* dh = g_denom + (size_t)(b * H_ + h) * S_;
    const float* cs = g_colsum + (b << 10);
#pragma unroll
    for (int mt = 0; mt < 2; mt++) {
        int r0 = i0 + wm * 32 + mt * 16 + (lane >> 2);
        float d0 = dh[r0], d1 = dh[r0 + 8];
        float q0 = (d0 > 0.f) ? (1.0f / d0) : 0.f;
        float q1 = (d1 > 0.f) ? (1.0f / d1) : 0.f;
#pragma unroll
        for (int nt = 0; nt < 8; nt++) {
            int c = c0 + wn * 64 + nt * 8 + (lane & 3) * 2;
            float* a4 = acc[mt][nt];
            float2 o0, o1;
            if (d0 > 0.f) { o0 = make_float2(a4[0] * q0, a4[1] * q0); }
            else {
                float2 f = *(const float2*)(cs + c);
                o0 = make_float2(f.x * (1.0f / S_), f.y * (1.0f / S_));
            }
            if (d1 > 0.f) { o1 = make_float2(a4[2] * q1, a4[3] * q1); }
            else {
                float2 f = *(const float2*)(cs + c);
                o1 = make_float2(f.x * (1.0f / S_), f.y * (1.0f / S_));
            }
            *(float2*)(out + (size_t)(b * S_ + r0) * DOUT + c) = o0;
            *(float2*)(out + (size_t)(b * S_ + r0 + 8) * DOUT + c) = o1;
        }
    }
}

// ============================================================================
extern "C" void kernel_launch(void* const* d_in, const int* in_sizes, int n_in,
                              void* d_out, int out_size) {
    const float* x    = (const float*)d_in[0];  // [B,S,DIN]
    const float* mask = (const float*)d_in[1];  // [B,S]
    const int*   adj  = (const int*)d_in[2];    // [B,S,S]
    const float* W    = (const float*)d_in[3];  // [DIN,DOUT]
    const float* attw = (const float*)d_in[4];  // [2*DATT]
    float* out = (float*)d_out;

    cudaFuncSetAttribute(proj_mma, cudaFuncAttributeMaxDynamicSharedMemorySize, PROJ_SMEM);
    cudaFuncSetAttribute(att_mma, cudaFuncAttributeMaxDynamicSharedMemorySize, ATT_SMEM);

    xsplit_in<<<(NTOK * DIN) / (256 * 8), 256>>>(x);
    wsplit<<<dim3(DOUT / 32, DIN / 32), dim3(32, 8)>>>(W);
    adjbf_kernel<<<(B_ * S_ * S_) / (256 * 8), 256>>>(adj, mask);
    proj_mma<<<dim3(DOUT / 128, NTOK / 128), 256, PROJ_SMEM>>>();
    s2_kernel<<<(B_ * H_ * S_) / 8, 256>>>(attw);
    exp_kernel<<<B_ * H_, 512>>>(mask);
    colsum_kernel<<<(B_ * DOUT) / 256, 256>>>();
    denom_kernel<<<B_ * (S_ / 32), 256>>>(adj, mask);
    xsplit_s<<<dim3(NTOK / 32, DOUT / 32), dim3(32, 8)>>>();
    att_mma<<<dim3(H_, S_ / 128, B_), 256, ATT_SMEM>>>(out);
}